// round 1
// baseline (speedup 1.0000x reference)
#include <cuda_runtime.h>

// Problem constants (fixed shapes from the reference)
#define BB    4
#define CC    256
#define HH    128
#define WW    256
#define NG    4        // groups
#define CG    64       // channels per group
#define TAPS  9        // window (1,9)
#define PADX  4        // (wx/2)*dilate
#define TW    64       // output x-tile per block
#define EXT   (TW + TAPS - 1)   // 72 halo columns
#define WSTR  76                // smem row stride (16B-aligned)
#define HWSZ  (HH * WW)

__global__ __launch_bounds__(256)
void crestereo_corr_kernel(const float* __restrict__ left,
                           const float* __restrict__ right,
                           const float* __restrict__ flow,
                           float* __restrict__ out)
{
    __shared__ int   s_idx[4][EXT];                    // 4 bilinear corner indices per halo col
    __shared__ float s_wt[4][EXT];                     // 4 (zero-masked) weights per halo col
    __shared__ __align__(16) float s_warp[CG * WSTR];  // warped tile for current group
    __shared__ float s_part[8 * 16 * 36];              // partial sums (8 cq-pairs)

    const int tid = threadIdx.x;
    const int x0t = blockIdx.x * TW;
    const int y   = blockIdx.y;
    const int b   = blockIdx.z;

    // ---------------- Phase A: per-column bilinear sample info ----------------
    // Column e corresponds to replicate-padded output column: xo = clamp(x0t + e - PADX)
    if (tid < EXT) {
        int xo = x0t + tid - PADX;
        xo = max(0, min(WW - 1, xo));
        const float fx = flow[((size_t)(b * 2 + 0) * HH + y) * WW + xo];
        const float fy = flow[((size_t)(b * 2 + 1) * HH + y) * WW + xo];
        float cx = (float)xo + fx;
        float cy = (float)y + fy;
        float fx0 = floorf(cx), fy0 = floorf(cy);
        float ax = cx - fx0, ay = cy - fy0;     // frac parts
        int ix0 = (int)fx0, iy0 = (int)fy0;
        int ix1 = ix0 + 1, iy1 = iy0 + 1;
        float wx0 = 1.f - ax, wy0 = 1.f - ay;
        int cx0 = max(0, min(WW - 1, ix0));
        int cx1 = max(0, min(WW - 1, ix1));
        int cy0 = max(0, min(HH - 1, iy0));
        int cy1 = max(0, min(HH - 1, iy1));
        bool vx0 = (ix0 >= 0) && (ix0 <= WW - 1);
        bool vx1 = (ix1 >= 0) && (ix1 <= WW - 1);
        bool vy0 = (iy0 >= 0) && (iy0 <= HH - 1);
        bool vy1 = (iy1 >= 0) && (iy1 <= HH - 1);
        s_idx[0][tid] = cy0 * WW + cx0;
        s_idx[1][tid] = cy0 * WW + cx1;
        s_idx[2][tid] = cy1 * WW + cx0;
        s_idx[3][tid] = cy1 * WW + cx1;
        s_wt[0][tid] = (vx0 && vy0) ? wx0 * wy0 : 0.f;
        s_wt[1][tid] = (vx1 && vy0) ? ax  * wy0 : 0.f;
        s_wt[2][tid] = (vx0 && vy1) ? wx0 * ay  : 0.f;
        s_wt[3][tid] = (vx1 && vy1) ? ax  * ay  : 0.f;
    }

    const int slot   = tid & 15;   // x slot: owns columns [slot*4, slot*4+4)
    const int cq     = tid >> 4;   // 0..15: owns channels [cq*4, cq*4+4)
    const int xl     = slot * 4;
    const int warpid = tid >> 5;   // cq-pair index after shfl reduce

    for (int g = 0; g < NG; ++g) {
        __syncthreads();   // A done (g=0); prev C done reading s_warp; prev R done reading s_part

        // ------------- Phase B: bilinear-warp the group's tile into smem -------------
        const float* rbase = right + (size_t)(b * CC + g * CG) * HWSZ;
        for (int i = tid; i < CG * EXT; i += 256) {
            int c = i / EXT;
            int e = i - c * EXT;
            const float* pl = rbase + (size_t)c * HWSZ;
            float v = s_wt[0][e] * __ldg(pl + s_idx[0][e])
                    + s_wt[1][e] * __ldg(pl + s_idx[1][e])
                    + s_wt[2][e] * __ldg(pl + s_idx[2][e])
                    + s_wt[3][e] * __ldg(pl + s_idx[3][e]);
            s_warp[c * WSTR + e] = v;
        }
        __syncthreads();

        // ------------- Phase C: 9-tap correlation, 4 x-cols x 4 channels per thread -------------
        float acc[4][TAPS];
        #pragma unroll
        for (int xi = 0; xi < 4; ++xi)
            #pragma unroll
            for (int t = 0; t < TAPS; ++t) acc[xi][t] = 0.f;

        const float* lp = left + ((size_t)(b * CC + g * CG + cq * 4) * HH + y) * WW + x0t + xl;
        #pragma unroll
        for (int ci = 0; ci < 4; ++ci) {
            float4 lv = *reinterpret_cast<const float4*>(lp + (size_t)ci * HWSZ);
            const float* wr = &s_warp[(cq * 4 + ci) * WSTR + xl];
            float4 w0 = *reinterpret_cast<const float4*>(wr);
            float4 w1 = *reinterpret_cast<const float4*>(wr + 4);
            float4 w2 = *reinterpret_cast<const float4*>(wr + 8);
            float win[12] = {w0.x, w0.y, w0.z, w0.w,
                             w1.x, w1.y, w1.z, w1.w,
                             w2.x, w2.y, w2.z, w2.w};
            float lvv[4] = {lv.x, lv.y, lv.z, lv.w};
            #pragma unroll
            for (int xi = 0; xi < 4; ++xi)
                #pragma unroll
                for (int t = 0; t < TAPS; ++t)
                    acc[xi][t] += lvv[xi] * win[xi + t];
        }

        // pair-reduce the two cq's sharing a warp (lane xor 16)
        #pragma unroll
        for (int xi = 0; xi < 4; ++xi)
            #pragma unroll
            for (int t = 0; t < TAPS; ++t)
                acc[xi][t] += __shfl_xor_sync(0xffffffffu, acc[xi][t], 16);

        if ((tid & 16) == 0) {
            float* pp = &s_part[(warpid * 16 + slot) * 36];
            #pragma unroll
            for (int xi = 0; xi < 4; ++xi)
                #pragma unroll
                for (int t = 0; t < TAPS; ++t)
                    pp[xi * TAPS + t] = acc[xi][t];
        }
        __syncthreads();

        // ------------- Reduce 8 partials + coalesced store -------------
        // addr = p*576 + 9*x + t-major trick: for fixed t, lane x -> addr 9x (gcd(9,32)=1) => conflict-free
        for (int j = tid; j < TAPS * TW; j += 256) {
            int x  = j & (TW - 1);
            int t  = j >> 6;
            int sl = x >> 2;
            int xi = x & 3;
            int k  = xi * TAPS + t;
            float s = 0.f;
            #pragma unroll
            for (int p = 0; p < 8; ++p)
                s += s_part[(p * 16 + sl) * 36 + k];
            out[(((size_t)b * (NG * TAPS) + g * TAPS + t) * HH + y) * WW + x0t + x] = s * (1.f / CG);
        }
    }
}

extern "C" void kernel_launch(void* const* d_in, const int* in_sizes, int n_in,
                              void* d_out, int out_size) {
    const float* left  = (const float*)d_in[0];
    const float* right = (const float*)d_in[1];
    const float* flow  = (const float*)d_in[2];
    float* out = (float*)d_out;
    dim3 grid(WW / TW, HH, BB);   // (4, 128, 4) = 2048 blocks
    crestereo_corr_kernel<<<grid, 256>>>(left, right, flow, out);
}